// round 1
// baseline (speedup 1.0000x reference)
#include <cuda_runtime.h>

// ---------------- problem constants ----------------
#define BB    16
#define CIN   4
#define DIN   64
#define C1    24       // 8 vector groups x 3
#define D1    34       // (64 + 10 - 7)/2 + 1
#define C2    16
#define D2    19       // (34 + 10 - 7)/2 + 1
#define KS    7
#define PAD   5
#define TAPS  343      // 7*7*7

#define D1SQ  (D1*D1)          // 1156
#define D1CU  (D1*D1*D1)       // 39304
#define D2SQ  (D2*D2)          // 361
#define D2CU  (D2*D2*D2)       // 6859

// conv1 tile: 8 x 8 x 4 outputs, 256 threads, 1 voxel/thread
#define T1X 8
#define T1Y 8
#define T1Z 4
#define S1X 21   // 2*(8-1)+7
#define S1Y 21
#define S1Z 13   // 2*(4-1)+7
#define IN1_ELEMS (S1X*S1Y*S1Z)     // 5733
#define W1_ELEMS  (TAPS*C1)         // 8232
#define CONV1_SMEM ((W1_ELEMS + IN1_ELEMS)*4)

// conv2 tile: 8 x 4 x 4 outputs, 128 threads, 1 voxel/thread
#define T2X 8
#define T2Y 4
#define T2Z 4
#define S2X 21
#define S2Y 13
#define S2Z 13
#define VCH_ELEMS (S2X*S2Y*S2Z)     // 3549
#define VCH_PAD   3552              // pad to 16B multiple
#define W2_STAGE  (49*9*C2)         // 7056 floats per (u,kz)
#define CONV2_SMEM ((3*VCH_PAD + W2_STAGE)*4)

// ---------------- scratch (static device memory; no allocs) ----------------
__device__ float  g_v[(size_t)BB*C1*D1CU];     // conv1 output, ~60 MB
__device__ float  g_y[(size_t)BB*C2*D2CU];     // conv2 output (pre-BN)
__device__ float  g_K1[CIN*TAPS*C1];           // [ci][tap][co]
__device__ float  g_K2[8*7*49*9*C2];           // [u][kz][kyx][ic9][co]
__device__ double g_sum[C2], g_sumsq[C2];
__device__ float  g_coef[2*C2];

// ---------------- packed f32x2 helpers ----------------
__device__ __forceinline__ void ffma2(unsigned long long &d,
                                      unsigned long long a,
                                      unsigned long long b) {
    asm("fma.rn.f32x2 %0, %1, %2, %0;" : "+l"(d) : "l"(a), "l"(b));
}
__device__ __forceinline__ unsigned long long mul2(unsigned long long a,
                                                   unsigned long long b) {
    unsigned long long r;
    asm("mul.rn.f32x2 %0, %1, %2;" : "=l"(r) : "l"(a), "l"(b));
    return r;
}
__device__ __forceinline__ unsigned long long splat2(float v) {
    unsigned long long r;
    unsigned int u = __float_as_uint(v);
    asm("mov.b64 %0, {%1, %1};" : "=l"(r) : "r"(u));
    return r;
}
__device__ __forceinline__ float2 unpack2(unsigned long long p) {
    unsigned int lo, hi;
    asm("mov.b64 {%0, %1}, %2;" : "=r"(lo), "=r"(hi) : "l"(p));
    return make_float2(__uint_as_float(lo), __uint_as_float(hi));
}

// ---------------- kernel generation ----------------
__global__ void zero_stats_kernel() {
    int t = threadIdx.x;
    if (t < C2) { g_sum[t] = 0.0; g_sumsq[t] = 0.0; }
}

// K1[ci][tap][co] ; co = u*3+i ; = sum_b W1[u][ci][b] * basis1[b][i][0][tap]
__global__ void gen_K1_kernel(const float* __restrict__ W1,
                              const float* __restrict__ basis1) {
    int idx = blockIdx.x * 256 + threadIdx.x;
    if (idx >= CIN*TAPS*C1) return;
    int co = idx % C1;
    int r  = idx / C1;
    int tap = r % TAPS;
    int ci  = r / TAPS;
    int u = co / 3, i = co % 3;
    float s = 0.f;
#pragma unroll
    for (int b = 0; b < 3; b++)
        s += W1[(u*CIN + ci)*3 + b] * basis1[(b*3 + i)*TAPS + tap];
    g_K1[idx] = s;
}

// K2[u][kz][kyx][ic9][co]; ic9: 0..2 = v components (from W2a/basis2a),
// 3..8 = symmetric products (i<=j), with folded (i,j)+(j,i) weights from W2b/basis2b.
__global__ void gen_K2_kernel(const float* __restrict__ W2a,
                              const float* __restrict__ basis2a,
                              const float* __restrict__ W2b,
                              const float* __restrict__ basis2b) {
    int idx = blockIdx.x * 256 + threadIdx.x;
    if (idx >= 8*7*49*9*C2) return;
    int co = idx & 15;
    int r  = idx >> 4;
    int ic = r % 9;  r /= 9;
    int kyx = r % 49; r /= 49;
    int kz = r % 7;
    int u  = r / 7;
    int tap = kz*49 + kyx;
    float s = 0.f;
    if (ic < 3) {
#pragma unroll
        for (int b = 0; b < 3; b++)
            s += W2a[(co*8 + u)*3 + b] * basis2a[(b*3 + ic)*TAPS + tap];
    } else {
        const int I[6] = {0,0,0,1,1,2};
        const int J[6] = {0,1,2,1,2,2};
        int i = I[ic-3], j = J[ic-3];
#pragma unroll
        for (int b = 0; b < 3; b++) {
            float w  = W2b[(co*8 + u)*3 + b];
            float bs = basis2b[(b*9 + i*3 + j)*TAPS + tap];
            if (i != j) bs += basis2b[(b*9 + j*3 + i)*TAPS + tap];
            s += w * bs;
        }
    }
    g_K2[idx] = s;
}

// ---------------- conv1: s[16,4,64^3] -> v[16,24,34^3] ----------------
__global__ __launch_bounds__(256)
void conv1_kernel(const float* __restrict__ s) {
    extern __shared__ float sm[];
    float* smw = sm;                 // W1_ELEMS
    float* smi = sm + W1_ELEMS;      // IN1_ELEMS

    int tid = threadIdx.x;
    int b  = blockIdx.z / 9;
    int tz = blockIdx.z % 9;
    int ox0 = blockIdx.x * T1X, oy0 = blockIdx.y * T1Y, oz0 = tz * T1Z;
    int ix0 = 2*ox0 - PAD, iy0 = 2*oy0 - PAD, iz0 = 2*oz0 - PAD;
    int lx = tid & 7, ly = (tid >> 3) & 7, lz = tid >> 6;

    unsigned long long acc[12];
#pragma unroll
    for (int q = 0; q < 12; q++) acc[q] = 0ULL;

    for (int ci = 0; ci < CIN; ci++) {
        __syncthreads();
        for (int t = tid; t < W1_ELEMS; t += 256)
            smw[t] = g_K1[ci*W1_ELEMS + t];
        const float* sp = s + ((size_t)b*CIN + ci) * (DIN*DIN*DIN);
        for (int t = tid; t < IN1_ELEMS; t += 256) {
            int dx = t % S1X;
            int r  = t / S1X;
            int dy = r % S1Y;
            int dz = r / S1Y;
            int ix = ix0 + dx, iy = iy0 + dy, iz = iz0 + dz;
            float v = 0.f;
            if ((unsigned)ix < DIN && (unsigned)iy < DIN && (unsigned)iz < DIN)
                v = sp[((size_t)iz*DIN + iy)*DIN + ix];
            smi[t] = v;
        }
        __syncthreads();

        int zb = 2*lz, yb = 2*ly, xb = 2*lx;
#pragma unroll 1
        for (int kz = 0; kz < 7; kz++) {
#pragma unroll 1
            for (int ky = 0; ky < 7; ky++) {
                const float* rowi = &smi[(zb+kz)*(S1X*S1Y) + (yb+ky)*S1X + xb];
                const ulonglong2* wrow =
                    (const ulonglong2*)&smw[(kz*7 + ky)*7*C1];
#pragma unroll
                for (int kx = 0; kx < 7; kx++) {
                    unsigned long long a = splat2(rowi[kx]);
                    const ulonglong2* wp = wrow + kx*6;
#pragma unroll
                    for (int q = 0; q < 6; q++) {
                        ulonglong2 w = wp[q];
                        ffma2(acc[2*q],   a, w.x);
                        ffma2(acc[2*q+1], a, w.y);
                    }
                }
            }
        }
    }

    int ox = ox0 + lx, oy = oy0 + ly, oz = oz0 + lz;
    if (ox < D1 && oy < D1 && oz < D1) {
        size_t base = ((size_t)b*C1*D1 + oz)*D1SQ + oy*D1 + ox;
#pragma unroll
        for (int q = 0; q < 12; q++) {
            float2 f = unpack2(acc[q]);
            g_v[base + (size_t)(2*q)  *D1CU] = f.x;
            g_v[base + (size_t)(2*q+1)*D1CU] = f.y;
        }
    }
}

// ------- conv2 (+ fused tensor product + BN partial sums) -------
// v[16,24,34^3] -> y[16,16,19^3]
__global__ __launch_bounds__(128)
void conv2_kernel() {
    extern __shared__ float sm[];
    float* sv  = sm;                   // 3 * VCH_PAD
    float* smw = sm + 3*VCH_PAD;       // W2_STAGE

    int tid = threadIdx.x;
    int b  = blockIdx.z / 5;
    int tz = blockIdx.z % 5;
    int ox0 = blockIdx.x * T2X, oy0 = blockIdx.y * T2Y, oz0 = tz * T2Z;
    int ix0 = 2*ox0 - PAD, iy0 = 2*oy0 - PAD, iz0 = 2*oz0 - PAD;
    int lx = tid & 7, ly = (tid >> 3) & 3, lz = tid >> 5;

    unsigned long long acc[8];
#pragma unroll
    for (int q = 0; q < 8; q++) acc[q] = 0ULL;

    for (int u = 0; u < 8; u++) {
        __syncthreads();
        // load 3 vector-component tiles with zero padding
        for (int c = 0; c < 3; c++) {
            const float* vp = g_v + ((size_t)b*C1 + u*3 + c) * D1CU;
            for (int t = tid; t < VCH_ELEMS; t += 128) {
                int dx = t % S2X;
                int r  = t / S2X;
                int dy = r % S2Y;
                int dz = r / S2Y;
                int ix = ix0 + dx, iy = iy0 + dy, iz = iz0 + dz;
                float val = 0.f;
                if ((unsigned)ix < D1 && (unsigned)iy < D1 && (unsigned)iz < D1)
                    val = vp[((size_t)iz*D1 + iy)*D1 + ix];
                sv[c*VCH_PAD + dz*(S2X*S2Y) + dy*S2X + dx] = val;
            }
        }
        for (int kz = 0; kz < 7; kz++) {
            __syncthreads();
            const float* wsrc = g_K2 + (size_t)(u*7 + kz)*W2_STAGE;
            for (int t = tid; t < W2_STAGE; t += 128) smw[t] = wsrc[t];
            __syncthreads();

            int z = 2*lz + kz;
            const float* p0 = &sv[0*VCH_PAD + z*(S2X*S2Y) + (2*ly)*S2X + 2*lx];
            const float* p1 = p0 + VCH_PAD;
            const float* p2 = p1 + VCH_PAD;
#pragma unroll 1
            for (int ky = 0; ky < 7; ky++) {
#pragma unroll 1
                for (int kx = 0; kx < 7; kx++) {
                    int off = ky*S2X + kx;
                    unsigned long long pk[9];
                    pk[0] = splat2(p0[off]);
                    pk[1] = splat2(p1[off]);
                    pk[2] = splat2(p2[off]);
                    pk[3] = mul2(pk[0], pk[0]);
                    pk[4] = mul2(pk[0], pk[1]);
                    pk[5] = mul2(pk[0], pk[2]);
                    pk[6] = mul2(pk[1], pk[1]);
                    pk[7] = mul2(pk[1], pk[2]);
                    pk[8] = mul2(pk[2], pk[2]);
                    const ulonglong2* wp =
                        (const ulonglong2*)&smw[(ky*7 + kx)*(9*C2)];
#pragma unroll
                    for (int ic = 0; ic < 9; ic++) {
                        ulonglong2 w0 = wp[ic*4+0];
                        ulonglong2 w1 = wp[ic*4+1];
                        ulonglong2 w2 = wp[ic*4+2];
                        ulonglong2 w3 = wp[ic*4+3];
                        ffma2(acc[0], pk[ic], w0.x);
                        ffma2(acc[1], pk[ic], w0.y);
                        ffma2(acc[2], pk[ic], w1.x);
                        ffma2(acc[3], pk[ic], w1.y);
                        ffma2(acc[4], pk[ic], w2.x);
                        ffma2(acc[5], pk[ic], w2.y);
                        ffma2(acc[6], pk[ic], w3.x);
                        ffma2(acc[7], pk[ic], w3.y);
                    }
                }
            }
        }
    }

    int ox = ox0 + lx, oy = oy0 + ly, oz = oz0 + lz;
    bool valid = (ox < D2 && oy < D2 && oz < D2);
    float yv[16];
#pragma unroll
    for (int q = 0; q < 8; q++) {
        float2 f = unpack2(acc[q]);
        yv[2*q] = f.x; yv[2*q+1] = f.y;
    }
    if (valid) {
        size_t base = ((size_t)b*C2*D2 + oz)*D2SQ + oy*D2 + ox;
#pragma unroll
        for (int co = 0; co < C2; co++)
            g_y[base + (size_t)co*D2CU] = yv[co];
    }

    // BN partial sums: warp reduce -> smem -> one double atomic per channel
    __syncthreads();
    float* red = sm;    // reuse (256 floats)
    int lane = tid & 31, wid = tid >> 5;
#pragma unroll
    for (int co = 0; co < C2; co++) {
        float v  = valid ? yv[co] : 0.f;
        float v2 = v*v;
#pragma unroll
        for (int o = 16; o > 0; o >>= 1) {
            v  += __shfl_down_sync(0xffffffffu, v,  o);
            v2 += __shfl_down_sync(0xffffffffu, v2, o);
        }
        if (lane == 0) {
            red[wid*32 + co]       = v;
            red[128 + wid*32 + co] = v2;
        }
    }
    __syncthreads();
    if (tid < C2) {
        float s1 = 0.f, s2 = 0.f;
#pragma unroll
        for (int w = 0; w < 4; w++) {
            s1 += red[w*32 + tid];
            s2 += red[128 + w*32 + tid];
        }
        atomicAdd(&g_sum[tid],   (double)s1);
        atomicAdd(&g_sumsq[tid], (double)s2);
    }
}

// ---------------- BN coefficients ----------------
__global__ void coef_kernel(const float* __restrict__ gamma,
                            const float* __restrict__ beta,
                            const float* __restrict__ bias) {
    int c = threadIdx.x;
    if (c < C2) {
        double N = (double)BB * (double)D2CU;
        double mean = g_sum[c] / N;
        double var  = g_sumsq[c] / N - mean*mean;
        float a = gamma[c] * rsqrtf((float)var + 1e-5f);
        g_coef[c]       = a;
        g_coef[C2 + c]  = beta[c] - a * (float)mean + bias[c];
    }
}

// ---------------- BN apply + bias + relu ----------------
__global__ void apply_kernel(float* __restrict__ out) {
    int idx = blockIdx.x * 256 + threadIdx.x;   // exactly covers 16*16*6859
    int c = (idx / D2CU) & 15;
    float a = g_coef[c], b = g_coef[C2 + c];
    out[idx] = fmaxf(fmaf(a, g_y[idx], b), 0.f);
}

// ---------------- launch ----------------
extern "C" void kernel_launch(void* const* d_in, const int* in_sizes, int n_in,
                              void* d_out, int out_size) {
    (void)in_sizes; (void)n_in; (void)out_size;
    const float* s       = (const float*)d_in[0];
    const float* basis1  = (const float*)d_in[1];
    const float* W1      = (const float*)d_in[2];
    const float* basis2a = (const float*)d_in[3];
    const float* basis2b = (const float*)d_in[4];
    const float* W2a     = (const float*)d_in[5];
    const float* W2b     = (const float*)d_in[6];
    const float* gamma   = (const float*)d_in[7];
    const float* beta    = (const float*)d_in[8];
    const float* bias    = (const float*)d_in[9];
    float* out = (float*)d_out;

    cudaFuncSetAttribute(conv1_kernel,
        cudaFuncAttributeMaxDynamicSharedMemorySize, CONV1_SMEM);
    cudaFuncSetAttribute(conv2_kernel,
        cudaFuncAttributeMaxDynamicSharedMemorySize, CONV2_SMEM);

    zero_stats_kernel<<<1, 32>>>();
    gen_K1_kernel<<<(CIN*TAPS*C1 + 255)/256, 256>>>(W1, basis1);
    gen_K2_kernel<<<(8*7*49*9*C2 + 255)/256, 256>>>(W2a, basis2a, W2b, basis2b);
    conv1_kernel<<<dim3(5, 5, BB*9), 256, CONV1_SMEM>>>(s);
    conv2_kernel<<<dim3(3, 5, BB*5), 128, CONV2_SMEM>>>();
    coef_kernel<<<1, C2>>>(gamma, beta, bias);
    apply_kernel<<<D2CU, 256>>>(out);
}

// round 2
// speedup vs baseline: 1.6537x; 1.6537x over previous
#include <cuda_runtime.h>

// ---------------- problem constants ----------------
#define BB    16
#define CIN   4
#define DIN   64
#define C1    24       // 8 vector groups x 3
#define D1    34
#define C2    16
#define D2    19
#define PAD   5
#define TAPS  343

#define D1SQ  (D1*D1)
#define D1CU  (D1*D1*D1)
#define D2SQ  (D2*D2)
#define D2CU  (D2*D2*D2)

// conv1: tile 9x9x9 outputs; 256 threads (9x9x3 used), V=3 voxels/thread in z
#define S1N   23                 // 2*8+7
#define IN1_N (S1N*S1N*S1N)      // 12167
#define W1_ELEMS (TAPS*C1)       // 8232
#define CONV1_SMEM ((W1_ELEMS + IN1_N)*4)   // 81596 B

// conv2: tile 5x5x10 outputs; 128 threads (5x5x5 used), V=2 voxels/thread in z
#define S2XN  15                 // 2*4+7
#define S2ZN  25                 // 2*9+7
#define VCH_N (S2XN*S2XN*S2ZN)   // 5625
#define VCH_PADN 5632
#define W2_STAGE (49*9*C2)       // 7056 floats per (u,kz)
#define CONV2_SMEM ((3*VCH_PADN + W2_STAGE)*4)  // 95808 B

// ---------------- scratch ----------------
__device__ float  g_v[(size_t)BB*C1*D1CU];
__device__ float  g_y[(size_t)BB*C2*D2CU];
__device__ float  g_K1[CIN*TAPS*C1];           // [ci][tap][co]
__device__ float  g_K2[8*7*49*9*C2];           // [u][kz][kyx][ic9][co]
__device__ double g_sum[C2], g_sumsq[C2];
__device__ float  g_coef[2*C2];

// ---------------- packed f32x2 helpers ----------------
__device__ __forceinline__ void ffma2(unsigned long long &d,
                                      unsigned long long a,
                                      unsigned long long b) {
    asm("fma.rn.f32x2 %0, %1, %2, %0;" : "+l"(d) : "l"(a), "l"(b));
}
__device__ __forceinline__ unsigned long long mul2(unsigned long long a,
                                                   unsigned long long b) {
    unsigned long long r;
    asm("mul.rn.f32x2 %0, %1, %2;" : "=l"(r) : "l"(a), "l"(b));
    return r;
}
__device__ __forceinline__ unsigned long long splat2(float v) {
    unsigned long long r;
    unsigned int u = __float_as_uint(v);
    asm("mov.b64 %0, {%1, %1};" : "=l"(r) : "r"(u));
    return r;
}
__device__ __forceinline__ float2 unpack2(unsigned long long p) {
    unsigned int lo, hi;
    asm("mov.b64 {%0, %1}, %2;" : "=r"(lo), "=r"(hi) : "l"(p));
    return make_float2(__uint_as_float(lo), __uint_as_float(hi));
}

// ---------------- small kernels ----------------
__global__ void zero_stats_kernel() {
    int t = threadIdx.x;
    if (t < C2) { g_sum[t] = 0.0; g_sumsq[t] = 0.0; }
}

__global__ void gen_K1_kernel(const float* __restrict__ W1,
                              const float* __restrict__ basis1) {
    int idx = blockIdx.x * 256 + threadIdx.x;
    if (idx >= CIN*TAPS*C1) return;
    int co = idx % C1;
    int r  = idx / C1;
    int tap = r % TAPS;
    int ci  = r / TAPS;
    int u = co / 3, i = co % 3;
    float s = 0.f;
#pragma unroll
    for (int b = 0; b < 3; b++)
        s += W1[(u*CIN + ci)*3 + b] * basis1[(b*3 + i)*TAPS + tap];
    g_K1[idx] = s;
}

__global__ void gen_K2_kernel(const float* __restrict__ W2a,
                              const float* __restrict__ basis2a,
                              const float* __restrict__ W2b,
                              const float* __restrict__ basis2b) {
    int idx = blockIdx.x * 256 + threadIdx.x;
    if (idx >= 8*7*49*9*C2) return;
    int co = idx & 15;
    int r  = idx >> 4;
    int ic = r % 9;  r /= 9;
    int kyx = r % 49; r /= 49;
    int kz = r % 7;
    int u  = r / 7;
    int tap = kz*49 + kyx;
    float s = 0.f;
    if (ic < 3) {
#pragma unroll
        for (int b = 0; b < 3; b++)
            s += W2a[(co*8 + u)*3 + b] * basis2a[(b*3 + ic)*TAPS + tap];
    } else {
        const int I[6] = {0,0,0,1,1,2};
        const int J[6] = {0,1,2,1,2,2};
        int i = I[ic-3], j = J[ic-3];
#pragma unroll
        for (int b = 0; b < 3; b++) {
            float w  = W2b[(co*8 + u)*3 + b];
            float bs = basis2b[(b*9 + i*3 + j)*TAPS + tap];
            if (i != j) bs += basis2b[(b*9 + j*3 + i)*TAPS + tap];
            s += w * bs;
        }
    }
    g_K2[idx] = s;
}

// ---------------- conv1: s[16,4,64^3] -> v[16,24,34^3] ----------------
// tile 9x9x9, threads 256 (243 active: 9x9x3), V=3 z-voxels per thread
__global__ __launch_bounds__(256, 2)
void conv1_kernel(const float* __restrict__ s) {
    extern __shared__ float sm[];
    float* smw = sm;                 // W1_ELEMS
    float* smi = sm + W1_ELEMS;      // IN1_N

    int tid = threadIdx.x;
    int b  = blockIdx.z >> 2;        // 4 z-tiles per image
    int tz = blockIdx.z & 3;
    int ox0 = blockIdx.x * 9, oy0 = blockIdx.y * 9, oz0 = tz * 9;
    int ix0 = 2*ox0 - PAD, iy0 = 2*oy0 - PAD, iz0 = 2*oz0 - PAD;

    int lx = tid % 9;
    int rr = tid / 9;
    int ly = rr % 9;
    int lz3 = rr / 9;                 // 0..3 (243..255 -> 3)
    bool live = (lz3 < 3);
    int lz = live ? lz3 : 0;

    unsigned long long acc[36];       // [k 0..2][12 channel-pairs]
#pragma unroll
    for (int q = 0; q < 36; q++) acc[q] = 0ULL;

    for (int ci = 0; ci < CIN; ci++) {
        __syncthreads();
        {   // stage weights (vectorized)
            const float4* src = (const float4*)(g_K1 + ci*W1_ELEMS);
            float4* dst = (float4*)smw;
            for (int t = tid; t < W1_ELEMS/4; t += 256) dst[t] = src[t];
        }
        {   // stage input tile with zero padding
            const float* sp = s + ((size_t)b*CIN + ci) * (DIN*DIN*DIN);
            for (int t = tid; t < IN1_N; t += 256) {
                int dx = t % S1N;
                int r  = t / S1N;
                int dy = r % S1N;
                int dz = r / S1N;
                int ix = ix0 + dx, iy = iy0 + dy, iz = iz0 + dz;
                float v = 0.f;
                if ((unsigned)ix < DIN && (unsigned)iy < DIN && (unsigned)iz < DIN)
                    v = sp[((size_t)iz*DIN + iy)*DIN + ix];
                smi[t] = v;
            }
        }
        __syncthreads();

        int zb = 6*lz, yb = 2*ly, xb = 2*lx;
#pragma unroll 1
        for (int kz = 0; kz < 7; kz++) {
#pragma unroll 1
            for (int ky = 0; ky < 7; ky++) {
                const float* r0 = &smi[(zb+kz)*(S1N*S1N) + (yb+ky)*S1N + xb];
                const ulonglong2* wrow =
                    (const ulonglong2*)&smw[(kz*7 + ky)*7*C1];
#pragma unroll
                for (int kx = 0; kx < 7; kx++) {
                    unsigned long long a0 = splat2(r0[kx]);
                    unsigned long long a1 = splat2(r0[kx + 2*S1N*S1N]);
                    unsigned long long a2 = splat2(r0[kx + 4*S1N*S1N]);
                    const ulonglong2* wp = wrow + kx*6;
#pragma unroll
                    for (int q = 0; q < 6; q++) {
                        ulonglong2 w = wp[q];
                        ffma2(acc[2*q],      a0, w.x);
                        ffma2(acc[2*q+1],    a0, w.y);
                        ffma2(acc[12+2*q],   a1, w.x);
                        ffma2(acc[12+2*q+1], a1, w.y);
                        ffma2(acc[24+2*q],   a2, w.x);
                        ffma2(acc[24+2*q+1], a2, w.y);
                    }
                }
            }
        }
    }

    int ox = ox0 + lx, oy = oy0 + ly;
    if (live && ox < D1 && oy < D1) {
#pragma unroll
        for (int k = 0; k < 3; k++) {
            int oz = oz0 + 3*lz + k;
            if (oz < D1) {
                size_t base = ((size_t)b*C1)*D1CU + (size_t)oz*D1SQ + oy*D1 + ox;
#pragma unroll
                for (int q = 0; q < 12; q++) {
                    float2 f = unpack2(acc[k*12 + q]);
                    g_v[base + (size_t)(2*q)  *D1CU] = f.x;
                    g_v[base + (size_t)(2*q+1)*D1CU] = f.y;
                }
            }
        }
    }
}

// ------- conv2 (+ fused tensor product + BN partial sums) -------
// tile 5x5x10, threads 128 (125 active: 5x5x5), V=2 z-voxels per thread
__global__ __launch_bounds__(128)
void conv2_kernel() {
    extern __shared__ float sm[];
    float* sv  = sm;                     // 3 * VCH_PADN
    float* smw = sm + 3*VCH_PADN;        // W2_STAGE

    int tid = threadIdx.x;
    int b  = blockIdx.z >> 1;            // 2 z-tiles per image
    int tz = blockIdx.z & 1;
    int ox0 = blockIdx.x * 5, oy0 = blockIdx.y * 5, oz0 = tz * 10;
    int ix0 = 2*ox0 - PAD, iy0 = 2*oy0 - PAD, iz0 = 2*oz0 - PAD;

    int lx = tid % 5;
    int rr = tid / 5;
    int ly = rr % 5;
    int lz5 = rr / 5;                    // 0..5 (125..127 -> 5)
    bool live = (lz5 < 5);
    int lz = live ? lz5 : 0;

    unsigned long long acc[16];          // [v 0..1][8 channel-pairs]
#pragma unroll
    for (int q = 0; q < 16; q++) acc[q] = 0ULL;

    for (int u = 0; u < 8; u++) {
        __syncthreads();
        // stage 3 vector-component tiles with zero padding
        for (int c = 0; c < 3; c++) {
            const float* vp = g_v + ((size_t)b*C1 + u*3 + c) * D1CU;
            for (int t = tid; t < VCH_N; t += 128) {
                int dx = t % S2XN;
                int r  = t / S2XN;
                int dy = r % S2XN;
                int dz = r / S2XN;
                int ix = ix0 + dx, iy = iy0 + dy, iz = iz0 + dz;
                float val = 0.f;
                if ((unsigned)ix < D1 && (unsigned)iy < D1 && (unsigned)iz < D1)
                    val = vp[((size_t)iz*D1 + iy)*D1 + ix];
                sv[c*VCH_PADN + dz*(S2XN*S2XN) + dy*S2XN + dx] = val;
            }
        }
        for (int kz = 0; kz < 7; kz++) {
            __syncthreads();
            {
                const float4* src =
                    (const float4*)(g_K2 + (size_t)(u*7 + kz)*W2_STAGE);
                float4* dst = (float4*)smw;
                for (int t = tid; t < W2_STAGE/4; t += 128) dst[t] = src[t];
            }
            __syncthreads();

            int z0 = 2*lz + kz;
            const float* p0 = &sv[z0*(S2XN*S2XN) + (2*ly)*S2XN + 2*lx];
#pragma unroll 1
            for (int ky = 0; ky < 7; ky++) {
#pragma unroll 1
                for (int kx = 0; kx < 7; kx++) {
                    int off = ky*S2XN + kx;
                    // voxel 0 inputs (3 components), voxel 1 at z+10
                    unsigned long long s00 = splat2(p0[off]);
                    unsigned long long s01 = splat2(p0[off + VCH_PADN]);
                    unsigned long long s02 = splat2(p0[off + 2*VCH_PADN]);
                    unsigned long long s10 = splat2(p0[off + 10*S2XN*S2XN]);
                    unsigned long long s11 = splat2(p0[off + 10*S2XN*S2XN + VCH_PADN]);
                    unsigned long long s12 = splat2(p0[off + 10*S2XN*S2XN + 2*VCH_PADN]);
                    unsigned long long pk0[9], pk1[9];
                    pk0[0] = s00; pk0[1] = s01; pk0[2] = s02;
                    pk0[3] = mul2(s00, s00);
                    pk0[4] = mul2(s00, s01);
                    pk0[5] = mul2(s00, s02);
                    pk0[6] = mul2(s01, s01);
                    pk0[7] = mul2(s01, s02);
                    pk0[8] = mul2(s02, s02);
                    pk1[0] = s10; pk1[1] = s11; pk1[2] = s12;
                    pk1[3] = mul2(s10, s10);
                    pk1[4] = mul2(s10, s11);
                    pk1[5] = mul2(s10, s12);
                    pk1[6] = mul2(s11, s11);
                    pk1[7] = mul2(s11, s12);
                    pk1[8] = mul2(s12, s12);
                    const ulonglong2* wp =
                        (const ulonglong2*)&smw[(ky*7 + kx)*(9*C2)];
#pragma unroll
                    for (int ic = 0; ic < 9; ic++) {
                        ulonglong2 w0 = wp[ic*4+0];
                        ulonglong2 w1 = wp[ic*4+1];
                        ulonglong2 w2 = wp[ic*4+2];
                        ulonglong2 w3 = wp[ic*4+3];
                        ffma2(acc[0], pk0[ic], w0.x);
                        ffma2(acc[1], pk0[ic], w0.y);
                        ffma2(acc[2], pk0[ic], w1.x);
                        ffma2(acc[3], pk0[ic], w1.y);
                        ffma2(acc[4], pk0[ic], w2.x);
                        ffma2(acc[5], pk0[ic], w2.y);
                        ffma2(acc[6], pk0[ic], w3.x);
                        ffma2(acc[7], pk0[ic], w3.y);
                        ffma2(acc[8],  pk1[ic], w0.x);
                        ffma2(acc[9],  pk1[ic], w0.y);
                        ffma2(acc[10], pk1[ic], w1.x);
                        ffma2(acc[11], pk1[ic], w1.y);
                        ffma2(acc[12], pk1[ic], w2.x);
                        ffma2(acc[13], pk1[ic], w2.y);
                        ffma2(acc[14], pk1[ic], w3.x);
                        ffma2(acc[15], pk1[ic], w3.y);
                    }
                }
            }
        }
    }

    int ox = ox0 + lx, oy = oy0 + ly;
    float yv[2][16];
#pragma unroll
    for (int v = 0; v < 2; v++)
#pragma unroll
        for (int q = 0; q < 8; q++) {
            float2 f = unpack2(acc[v*8 + q]);
            yv[v][2*q] = f.x; yv[v][2*q+1] = f.y;
        }

    bool validv[2];
#pragma unroll
    for (int v = 0; v < 2; v++) {
        int oz = oz0 + lz + 5*v;
        validv[v] = live && ox < D2 && oy < D2 && oz < D2;
        if (validv[v]) {
            size_t base = ((size_t)b*C2)*D2CU + (size_t)oz*D2SQ + oy*D2 + ox;
#pragma unroll
            for (int co = 0; co < C2; co++)
                g_y[base + (size_t)co*D2CU] = yv[v][co];
        }
    }

    // BN partial sums
    __syncthreads();
    float* red = sm;    // reuse
    int lane = tid & 31, wid = tid >> 5;
#pragma unroll
    for (int co = 0; co < C2; co++) {
        float vsum  = 0.f, v2sum = 0.f;
#pragma unroll
        for (int v = 0; v < 2; v++) {
            float x = validv[v] ? yv[v][co] : 0.f;
            vsum += x; v2sum += x*x;
        }
#pragma unroll
        for (int o = 16; o > 0; o >>= 1) {
            vsum  += __shfl_down_sync(0xffffffffu, vsum,  o);
            v2sum += __shfl_down_sync(0xffffffffu, v2sum, o);
        }
        if (lane == 0) {
            red[wid*32 + co]       = vsum;
            red[128 + wid*32 + co] = v2sum;
        }
    }
    __syncthreads();
    if (tid < C2) {
        float s1 = 0.f, s2 = 0.f;
#pragma unroll
        for (int w = 0; w < 4; w++) {
            s1 += red[w*32 + tid];
            s2 += red[128 + w*32 + tid];
        }
        atomicAdd(&g_sum[tid],   (double)s1);
        atomicAdd(&g_sumsq[tid], (double)s2);
    }
}

// ---------------- BN coefficients ----------------
__global__ void coef_kernel(const float* __restrict__ gamma,
                            const float* __restrict__ beta,
                            const float* __restrict__ bias) {
    int c = threadIdx.x;
    if (c < C2) {
        double N = (double)BB * (double)D2CU;
        double mean = g_sum[c] / N;
        double var  = g_sumsq[c] / N - mean*mean;
        float a = gamma[c] * rsqrtf((float)var + 1e-5f);
        g_coef[c]       = a;
        g_coef[C2 + c]  = beta[c] - a * (float)mean + bias[c];
    }
}

// ---------------- BN apply + bias + relu ----------------
__global__ void apply_kernel(float* __restrict__ out) {
    int idx = blockIdx.x * 256 + threadIdx.x;   // exactly 16*16*6859
    int c = (idx / D2CU) & 15;
    float a = g_coef[c], b = g_coef[C2 + c];
    out[idx] = fmaxf(fmaf(a, g_y[idx], b), 0.f);
}

// ---------------- launch ----------------
extern "C" void kernel_launch(void* const* d_in, const int* in_sizes, int n_in,
                              void* d_out, int out_size) {
    (void)in_sizes; (void)n_in; (void)out_size;
    const float* s       = (const float*)d_in[0];
    const float* basis1  = (const float*)d_in[1];
    const float* W1      = (const float*)d_in[2];
    const float* basis2a = (const float*)d_in[3];
    const float* basis2b = (const float*)d_in[4];
    const float* W2a     = (const float*)d_in[5];
    const float* W2b     = (const float*)d_in[6];
    const float* gamma   = (const float*)d_in[7];
    const float* beta    = (const float*)d_in[8];
    const float* bias    = (const float*)d_in[9];
    float* out = (float*)d_out;

    cudaFuncSetAttribute(conv1_kernel,
        cudaFuncAttributeMaxDynamicSharedMemorySize, CONV1_SMEM);
    cudaFuncSetAttribute(conv2_kernel,
        cudaFuncAttributeMaxDynamicSharedMemorySize, CONV2_SMEM);

    zero_stats_kernel<<<1, 32>>>();
    gen_K1_kernel<<<(CIN*TAPS*C1 + 255)/256, 256>>>(W1, basis1);
    gen_K2_kernel<<<(8*7*49*9*C2 + 255)/256, 256>>>(W2a, basis2a, W2b, basis2b);
    conv1_kernel<<<dim3(4, 4, BB*4), 256, CONV1_SMEM>>>(s);
    conv2_kernel<<<dim3(4, 4, BB*2), 128, CONV2_SMEM>>>();
    coef_kernel<<<1, C2>>>(gamma, beta, bias);
    apply_kernel<<<D2CU, 256>>>(out);
}